// round 14
// baseline (speedup 1.0000x reference)
#include <cuda_runtime.h>
#include <cstdint>

#define BATCH    1024
#define VOCAB    100000
#define DIM      128
#define NSEG     3
#define NBINS    2048
#define HOTCAP   3072
#define BCAP     96
#define NTHREADS 512
#define CUT0 100
#define CUT1 500
#define CUT2 1000
#define TGUESS 2.0f          // rank-1000 of 100k N(0,1) ~ 2.33; P(v>2)~2.3% -> ~2275 cands

__device__ int   g_cnt[BATCH];
__device__ int   g_sidx[BATCH * HOTCAP];
__device__ float g_sval[BATCH * HOTCAP];

struct HxCtx {
    cudaStream_t s2;
    cudaEvent_t e1, e2;
    HxCtx() {
        cudaStreamCreateWithFlags(&s2, cudaStreamNonBlocking);
        cudaEventCreateWithFlags(&e1, cudaEventDisableTiming);
        cudaEventCreateWithFlags(&e2, cudaEventDisableTiming);
    }
};
static HxCtx g_ctx;

__device__ __forceinline__ unsigned mono(float f) {
    unsigned u = __float_as_uint(f);
    return (u & 0x80000000u) ? ~u : (u | 0x80000000u);
}
__device__ __forceinline__ float unmono(unsigned m) {
    unsigned u = (m & 0x80000000u) ? (m ^ 0x80000000u) : ~m;
    return __uint_as_float(u);
}
__device__ __forceinline__ unsigned finebin(unsigned m) {
    unsigned fb = (m - 0xC0000000u) >> 13;       // BASE = mono(2.0f), 2048 bins
    return (fb > (NBINS - 1u)) ? (NBINS - 1u) : fb;
}

// ---------------------------------------------------------------------------
// Copy kernel: pure grid-stride 820 MB move. No branches in steady state.
// ---------------------------------------------------------------------------
__global__ void __launch_bounds__(256)
copy_kernel(const float4* __restrict__ src, float4* __restrict__ dst)
{
    const int N = BATCH * VOCAB / 4;             // 25,600,000
    const int stride = gridDim.x * blockDim.x;
    int j = blockIdx.x * blockDim.x + threadIdx.x;
    for (; j + 3 * stride < N; j += 4 * stride) {
        float4 a = __ldcs(&src[j]);
        float4 b = __ldcs(&src[j + stride]);
        float4 c = __ldcs(&src[j + 2 * stride]);
        float4 d = __ldcs(&src[j + 3 * stride]);
        __stcs(&dst[j],              a);
        __stcs(&dst[j + stride],     b);
        __stcs(&dst[j + 2 * stride], c);
        __stcs(&dst[j + 3 * stride], d);
    }
    for (; j < N; j += stride)
        __stcs(&dst[j], __ldcs(&src[j]));
}

// ---------------------------------------------------------------------------
// Scan NBINS-bin histogram descending with shfl; 4 bins per thread.
// ---------------------------------------------------------------------------
__device__ void scan_find(unsigned* hist, unsigned* warpsum, int tid,
                          int* s_bin, int* s_rank)
{
    const int lane = tid & 31, w = tid >> 5;
    unsigned c[4];
    unsigned chunk = 0;
#pragma unroll
    for (int j = 0; j < 4; j++) {
        c[j] = hist[NBINS - 1 - 4 * tid - j];
        chunk += c[j];
    }
    unsigned pfx = chunk;
#pragma unroll
    for (int off = 1; off < 32; off <<= 1) {
        unsigned n = __shfl_up_sync(0xFFFFFFFFu, pfx, off);
        if (lane >= off) pfx += n;
    }
    if (lane == 31) warpsum[w] = pfx;
    __syncthreads();
    if (w == 0) {
        unsigned s = (lane < 16) ? warpsum[lane] : 0u;
#pragma unroll
        for (int off = 1; off < 16; off <<= 1) {
            unsigned n = __shfl_up_sync(0xFFFFFFFFu, s, off);
            if (lane >= off) s += n;
        }
        if (lane < 16) warpsum[lane] = s;
    }
    __syncthreads();
    unsigned wbase = (w > 0) ? warpsum[w - 1] : 0u;
    unsigned incl = wbase + pfx;
    unsigned excl = incl - chunk;
    const unsigned Ks[3] = {CUT0, CUT1, CUT2};
#pragma unroll
    for (int kk = 0; kk < 3; kk++) {
        unsigned K = Ks[kk];
        if (excl < K && K <= incl) {
            unsigned cc = excl;
#pragma unroll
            for (int j = 0; j < 4; j++) {
                unsigned h = c[j];
                if (cc < K && K <= cc + h) {
                    s_bin[kk]  = NBINS - 1 - 4 * tid - j;
                    s_rank[kk] = (int)(K - cc);
                    break;
                }
                cc += h;
            }
        }
    }
    __syncthreads();
}

__device__ __forceinline__ void push_cand(float v, int gi,
                                          unsigned long long* hot, unsigned* hist,
                                          int& slot)
{
    unsigned m = mono(v);
    if (slot < HOTCAP) {
        hot[slot] = ((unsigned long long)m << 32) | (unsigned)(~gi);
        atomicAdd(&hist[finebin(m)], 1u);
    }
    slot++;
}

__device__ __forceinline__ void push_group(float4 v, unsigned m4, int gi,
                                           unsigned long long* hot, unsigned* hist,
                                           int& slot)
{
    if (m4 & 1) push_cand(v.x, gi + 0, hot, hist, slot);
    if (m4 & 2) push_cand(v.y, gi + 1, hot, hist, slot);
    if (m4 & 4) push_cand(v.z, gi + 2, hot, hist, slot);
    if (m4 & 8) push_cand(v.w, gi + 3, hot, hist, slot);
}

// ---------------------------------------------------------------------------
// Collect kernel: READ-ONLY. collect -> rh GEMV -> select -> dot -> scratch.
// Non-surviving candidates get their original value (identity overwrite later).
// ---------------------------------------------------------------------------
__global__ void __launch_bounds__(NTHREADS, 4)
collect_kernel(const float* __restrict__ logits,
               const float* __restrict__ emb,
               const float* __restrict__ hidden,
               const float* __restrict__ W,
               const float* __restrict__ bias)
{
    __shared__ unsigned long long hot[HOTCAP];       // 24 KB
    __shared__ unsigned hist[NBINS];                 // 8 KB
    __shared__ unsigned long long bbuf[3][BCAP];
    __shared__ unsigned warpsum[16];
    __shared__ float rh[NSEG * DIM];
    __shared__ float sbias[NSEG * DIM];
    __shared__ float hrow[DIM];
    __shared__ unsigned long long Tkey[3];
    __shared__ int s_bin[3];
    __shared__ int s_rank[3];
    __shared__ int bcnt[3];
    __shared__ int s_nhot;

    const int row = blockIdx.x;
    const int tid = threadIdx.x;
    const int lane = tid & 31;
    const int wid = tid >> 5;

    for (int i = tid; i < NBINS; i += NTHREADS) hist[i] = 0u;
    if (tid < DIM) hrow[tid] = hidden[(size_t)row * DIM + tid];
    if (tid < NSEG * DIM) sbias[tid] = bias[tid];
    if (tid == 0) { s_nhot = 0; }
    if (tid < 3) bcnt[tid] = 0;
    __syncthreads();

    const float4* row4 = (const float4*)(logits + (size_t)row * VOCAB);
    const int NV4 = VOCAB / 4;   // 25000

    // ------- Pass 1: read-only 2-way batched scan + warp-aggregated collect --
    for (int base = 0; base < NV4; base += NTHREADS * 2) {
        int i0 = base + tid;
        int i1 = base + NTHREADS + tid;
        bool ok0 = i0 < NV4, ok1 = i1 < NV4;
        float4 v0, v1;
        if (ok0) v0 = __ldcs(&row4[i0]);
        if (ok1) v1 = __ldcs(&row4[i1]);

        float M0 = ok0 ? fmaxf(fmaxf(v0.x, v0.y), fmaxf(v0.z, v0.w)) : -1e30f;
        float M1 = ok1 ? fmaxf(fmaxf(v1.x, v1.y), fmaxf(v1.z, v1.w)) : -1e30f;
        unsigned msk = 0;
        int cnt = 0;
        if (fmaxf(M0, M1) > TGUESS) {
            if (M0 > TGUESS)
                msk |= (v0.x > TGUESS) | ((v0.y > TGUESS) << 1)
                     | ((v0.z > TGUESS) << 2) | ((v0.w > TGUESS) << 3);
            if (M1 > TGUESS)
                msk |= ((v1.x > TGUESS) << 4) | ((v1.y > TGUESS) << 5)
                     | ((v1.z > TGUESS) << 6) | ((v1.w > TGUESS) << 7);
            cnt = __popc(msk);
        }

        if (__ballot_sync(0xFFFFFFFFu, cnt > 0)) {
            int pfx = cnt;
#pragma unroll
            for (int off = 1; off < 32; off <<= 1) {
                int n = __shfl_up_sync(0xFFFFFFFFu, pfx, off);
                if (lane >= off) pfx += n;
            }
            int total = __shfl_sync(0xFFFFFFFFu, pfx, 31);
            int wbase = 0;
            if (lane == 31) wbase = atomicAdd(&s_nhot, total);
            wbase = __shfl_sync(0xFFFFFFFFu, wbase, 31);
            int slot = wbase + pfx - cnt;
            if (cnt) {
                push_group(v0, msk & 0xF,        4 * i0, hot, hist, slot);
                push_group(v1, (msk >> 4) & 0xF, 4 * i1, hot, hist, slot);
            }
        }
    }
    __syncthreads();

    // ------- In-CTA rh GEMV: 16 warps x 24 outputs, ILP-4 load groups -------
    {
        const float4* W4 = (const float4*)W;
        const float4* h4 = (const float4*)hrow;
        float4 hv = h4[lane];
        const int o0 = wid * 24;
#pragma unroll
        for (int g = 0; g < 6; g++) {
            float4 wv[4];
#pragma unroll
            for (int k = 0; k < 4; k++)
                wv[k] = W4[(size_t)(o0 + g * 4 + k) * 32 + lane];
#pragma unroll
            for (int k = 0; k < 4; k++) {
                float p = wv[k].x * hv.x + wv[k].y * hv.y
                        + wv[k].z * hv.z + wv[k].w * hv.w;
                p += __shfl_xor_sync(0xFFFFFFFFu, p, 16);
                p += __shfl_xor_sync(0xFFFFFFFFu, p, 8);
                p += __shfl_xor_sync(0xFFFFFFFFu, p, 4);
                p += __shfl_xor_sync(0xFFFFFFFFu, p, 2);
                p += __shfl_xor_sync(0xFFFFFFFFu, p, 1);
                int o = o0 + g * 4 + k;
                if (lane == 0) rh[o] = p + sbias[o];
            }
        }
    }

    int nhot = s_nhot;
    bool fast = (nhot >= CUT2) && (nhot <= HOTCAP);

    if (fast) {
        scan_find(hist, warpsum, tid, s_bin, s_rank);
        const int b0 = s_bin[0], b1 = s_bin[1], b2 = s_bin[2];

        for (int i = tid; i < nhot; i += NTHREADS) {
            unsigned long long k = hot[i];
            int bin = (int)finebin((unsigned)(k >> 32));
            if (bin == b0) { int p = atomicAdd(&bcnt[0], 1); if (p < BCAP) bbuf[0][p] = k; }
            if (bin == b1) { int p = atomicAdd(&bcnt[1], 1); if (p < BCAP) bbuf[1][p] = k; }
            if (bin == b2) { int p = atomicAdd(&bcnt[2], 1); if (p < BCAP) bbuf[2][p] = k; }
        }
        __syncthreads();

#pragma unroll
        for (int kk = 0; kk < 3; kk++) {
            int n = bcnt[kk];
            if (n <= BCAP) {
                for (int i = tid; i < n; i += NTHREADS) {
                    unsigned long long k = bbuf[kk][i];
                    int cnt = 0;
                    for (int j = 0; j < n; j++)
                        if (bbuf[kk][j] > k) cnt++;
                    if (cnt + 1 == s_rank[kk]) Tkey[kk] = k;
                }
            } else {
                const int bk = s_bin[kk];
                for (int i = tid; i < nhot; i += NTHREADS) {
                    unsigned long long k = hot[i];
                    if ((int)finebin((unsigned)(k >> 32)) != bk) continue;
                    int cnt = 0;
                    for (int j = 0; j < nhot; j++) {
                        unsigned long long kj = hot[j];
                        if ((int)finebin((unsigned)(kj >> 32)) == bk && kj > k) cnt++;
                    }
                    if (cnt + 1 == s_rank[kk]) Tkey[kk] = k;
                }
            }
        }
        __syncthreads();
    } else {
        // ------- Fallback: full coarse histogram over the row (rare) -------
        for (int i = tid; i < NBINS; i += NTHREADS) hist[i] = 0u;
        if (tid == 0) s_nhot = 0;
        __syncthreads();
        for (int i = tid; i < NV4; i += NTHREADS) {
            float4 v = row4[i];
            atomicAdd(&hist[mono(v.x) >> 21], 1u);
            atomicAdd(&hist[mono(v.y) >> 21], 1u);
            atomicAdd(&hist[mono(v.z) >> 21], 1u);
            atomicAdd(&hist[mono(v.w) >> 21], 1u);
        }
        __syncthreads();
        scan_find(hist, warpsum, tid, s_bin, s_rank);
        const int cb2 = s_bin[2];
        for (int i = tid; i < NV4; i += NTHREADS) {
            float4 v = row4[i];
            float vals[4] = {v.x, v.y, v.z, v.w};
            int b4 = 4 * i;
#pragma unroll
            for (int j = 0; j < 4; j++) {
                unsigned m = mono(vals[j]);
                if ((int)(m >> 21) >= cb2) {
                    int p = atomicAdd(&s_nhot, 1);
                    if (p < HOTCAP)
                        hot[p] = ((unsigned long long)m << 32) | (unsigned)(~(b4 + j));
                }
            }
        }
        __syncthreads();
        nhot = (s_nhot < HOTCAP) ? s_nhot : HOTCAP;
        const int b0 = s_bin[0], b1 = s_bin[1], b2 = s_bin[2];
        for (int i = tid; i < nhot; i += NTHREADS) {
            unsigned long long k = hot[i];
            int bin = (int)(k >> 53);
            bool m0 = (bin == b0), m1 = (bin == b1), m2 = (bin == b2);
            if (m0 | m1 | m2) {
                int cnt = 0;
                for (int j = 0; j < nhot; j++) {
                    unsigned long long kj = hot[j];
                    if ((int)(kj >> 53) == bin && kj > k) cnt++;
                }
                int r = cnt + 1;
                if (m0 && r == s_rank[0]) Tkey[0] = k;
                if (m1 && r == s_rank[1]) Tkey[1] = k;
                if (m2 && r == s_rank[2]) Tkey[2] = k;
            }
        }
        __syncthreads();
    }

    const unsigned long long T0 = Tkey[0], T1 = Tkey[1], T2 = Tkey[2];
    if (tid == 0) g_cnt[row] = nhot;

    // ------- Dot phase: slot = hot index (no atomics).
    // Survivors get the rerank dot; non-survivors get their ORIGINAL value,
    // making the later scatter an identity overwrite for them.
    const int NW = NTHREADS / 32;
    const float4* emb4 = (const float4*)emb;
    const float4* rh4  = (const float4*)rh;
    int*   sidx = g_sidx + (size_t)row * HOTCAP;
    float* sval = g_sval + (size_t)row * HOTCAP;

    for (int s = wid * 2; s < nhot; s += NW * 2) {
        unsigned long long k[2];
        bool act[2], in[2];
        unsigned idx[2];
        float4 e[2];
        int seg[2];
#pragma unroll
        for (int j = 0; j < 2; j++) {
            int si = s + j;
            in[j] = si < nhot;
            k[j] = in[j] ? hot[si] : 0ull;
            act[j] = in[j] && (k[j] >= T2);
            idx[j] = ~(unsigned)k[j];
            if (act[j]) {
                seg[j] = (k[j] >= T0) ? 0 : ((k[j] >= T1) ? 1 : 2);
                e[j] = emb4[(size_t)idx[j] * (DIM / 4) + lane];
            }
        }
#pragma unroll
        for (int j = 0; j < 2; j++) {
            if (!in[j]) continue;
            float p;
            if (act[j]) {
                float4 r = rh4[seg[j] * (DIM / 4) + lane];
                p = e[j].x * r.x + e[j].y * r.y + e[j].z * r.z + e[j].w * r.w;
                p += __shfl_xor_sync(0xFFFFFFFFu, p, 16);
                p += __shfl_xor_sync(0xFFFFFFFFu, p, 8);
                p += __shfl_xor_sync(0xFFFFFFFFu, p, 4);
                p += __shfl_xor_sync(0xFFFFFFFFu, p, 2);
                p += __shfl_xor_sync(0xFFFFFFFFu, p, 1);
            } else {
                p = unmono((unsigned)(k[j] >> 32));
            }
            if (lane == 0) { sidx[s + j] = (int)idx[j]; sval[s + j] = p; }
        }
    }
}

// ---------------------------------------------------------------------------
// Scatter kernel: write results into the copied output.
// ---------------------------------------------------------------------------
__global__ void __launch_bounds__(256)
scatter_kernel(float* __restrict__ out)
{
    const int row = blockIdx.x;
    const int cnt = g_cnt[row];
    const int n = (cnt < HOTCAP) ? cnt : HOTCAP;
    const int*   sidx = g_sidx + (size_t)row * HOTCAP;
    const float* sval = g_sval + (size_t)row * HOTCAP;
    float* outrow = out + (size_t)row * VOCAB;
    for (int i = threadIdx.x; i < n; i += 256)
        outrow[sidx[i]] = sval[i];
}

extern "C" void kernel_launch(void* const* d_in, const int* in_sizes, int n_in,
                              void* d_out, int out_size)
{
    const float* hidden = nullptr;
    const float* logits = nullptr;
    const float* emb    = nullptr;
    const float* W      = nullptr;
    const float* bias   = nullptr;
    for (int i = 0; i < n_in; i++) {
        switch (in_sizes[i]) {
            case BATCH * DIM:      hidden = (const float*)d_in[i]; break;
            case BATCH * VOCAB:    logits = (const float*)d_in[i]; break;
            case VOCAB * DIM:      emb    = (const float*)d_in[i]; break;
            case NSEG * DIM * DIM: W      = (const float*)d_in[i]; break;
            case NSEG * DIM:       bias   = (const float*)d_in[i]; break;
        }
    }
    float* out = (float*)d_out;

    // Fork: pure copy concurrently with the read-only collect kernel.
    cudaEventRecord(g_ctx.e1, 0);
    cudaStreamWaitEvent(g_ctx.s2, g_ctx.e1, 0);
    copy_kernel<<<2048, 256, 0, g_ctx.s2>>>((const float4*)logits, (float4*)out);
    cudaEventRecord(g_ctx.e2, g_ctx.s2);

    collect_kernel<<<BATCH, NTHREADS>>>(logits, emb, hidden, W, bias);

    // Join: scatter needs both the copy and collect results.
    cudaStreamWaitEvent(0, g_ctx.e2, 0);
    scatter_kernel<<<BATCH, 256>>>(out);
}

// round 15
// speedup vs baseline: 1.5619x; 1.5619x over previous
#include <cuda_runtime.h>
#include <cstdint>

#define BATCH    1024
#define VOCAB    100000
#define DIM      128
#define NSEG     3
#define NBINS    2048
#define HOTCAP   3072
#define BCAP     96
#define NTHREADS 512
#define CUT0 100
#define CUT1 500
#define CUT2 1000
#define TGUESS 2.0f          // rank-1000 of 100k N(0,1) ~ 2.33; P(v>2)~2.3% -> ~2275 cands

__device__ __forceinline__ unsigned mono(float f) {
    unsigned u = __float_as_uint(f);
    return (u & 0x80000000u) ? ~u : (u | 0x80000000u);
}

__device__ __forceinline__ unsigned finebin(unsigned m) {
    unsigned fb = (m - 0xC0000000u) >> 13;       // BASE = mono(2.0f), 2048 bins
    return (fb > (NBINS - 1u)) ? (NBINS - 1u) : fb;
}

// ---------------------------------------------------------------------------
// Scan NBINS-bin histogram descending with shfl; 4 bins per thread.
// ---------------------------------------------------------------------------
__device__ void scan_find(unsigned* hist, unsigned* warpsum, int tid,
                          int* s_bin, int* s_rank)
{
    const int lane = tid & 31, w = tid >> 5;
    unsigned c[4];
    unsigned chunk = 0;
#pragma unroll
    for (int j = 0; j < 4; j++) {
        c[j] = hist[NBINS - 1 - 4 * tid - j];
        chunk += c[j];
    }
    unsigned pfx = chunk;
#pragma unroll
    for (int off = 1; off < 32; off <<= 1) {
        unsigned n = __shfl_up_sync(0xFFFFFFFFu, pfx, off);
        if (lane >= off) pfx += n;
    }
    if (lane == 31) warpsum[w] = pfx;
    __syncthreads();
    if (w == 0) {
        unsigned s = (lane < 16) ? warpsum[lane] : 0u;
#pragma unroll
        for (int off = 1; off < 16; off <<= 1) {
            unsigned n = __shfl_up_sync(0xFFFFFFFFu, s, off);
            if (lane >= off) s += n;
        }
        if (lane < 16) warpsum[lane] = s;
    }
    __syncthreads();
    unsigned wbase = (w > 0) ? warpsum[w - 1] : 0u;
    unsigned incl = wbase + pfx;
    unsigned excl = incl - chunk;
    const unsigned Ks[3] = {CUT0, CUT1, CUT2};
#pragma unroll
    for (int kk = 0; kk < 3; kk++) {
        unsigned K = Ks[kk];
        if (excl < K && K <= incl) {
            unsigned cc = excl;
#pragma unroll
            for (int j = 0; j < 4; j++) {
                unsigned h = c[j];
                if (cc < K && K <= cc + h) {
                    s_bin[kk]  = NBINS - 1 - 4 * tid - j;
                    s_rank[kk] = (int)(K - cc);
                    break;
                }
                cc += h;
            }
        }
    }
    __syncthreads();
}

__device__ __forceinline__ void push_cand(float v, int gi,
                                          unsigned long long* hot, unsigned* hist,
                                          int& slot)
{
    unsigned m = mono(v);
    if (slot < HOTCAP) {
        hot[slot] = ((unsigned long long)m << 32) | (unsigned)(~gi);
        atomicAdd(&hist[finebin(m)], 1u);
    }
    slot++;
}

__device__ __forceinline__ void push_group(float4 v, unsigned m4, int gi,
                                           unsigned long long* hot, unsigned* hist,
                                           int& slot)
{
    if (m4 & 1) push_cand(v.x, gi + 0, hot, hist, slot);
    if (m4 & 2) push_cand(v.y, gi + 1, hot, hist, slot);
    if (m4 & 4) push_cand(v.z, gi + 2, hot, hist, slot);
    if (m4 & 8) push_cand(v.w, gi + 3, hot, hist, slot);
}

// ---------------------------------------------------------------------------
// Single fused kernel: one CTA (512 thr) per row.
// pass 1 uses software-pipelined prefetch: loads for iter t+1 issue before
// stores/processing of iter t (4 loads in flight per warp).
// ---------------------------------------------------------------------------
__global__ void __launch_bounds__(NTHREADS, 3)
rerank_kernel(const float* __restrict__ logits,
              const float* __restrict__ emb,
              const float* __restrict__ hidden,
              const float* __restrict__ W,
              const float* __restrict__ bias,
              float* __restrict__ out)
{
    __shared__ unsigned long long hot[HOTCAP];       // 24 KB
    __shared__ unsigned hist[NBINS];                 // 8 KB
    __shared__ unsigned long long bbuf[3][BCAP];
    __shared__ unsigned warpsum[16];
    __shared__ float rh[NSEG * DIM];
    __shared__ float sbias[NSEG * DIM];
    __shared__ float hrow[DIM];
    __shared__ unsigned long long Tkey[3];
    __shared__ int s_bin[3];
    __shared__ int s_rank[3];
    __shared__ int bcnt[3];
    __shared__ int s_nhot;

    const int row = blockIdx.x;
    const int tid = threadIdx.x;
    const int lane = tid & 31;
    const int wid = tid >> 5;

    for (int i = tid; i < NBINS; i += NTHREADS) hist[i] = 0u;
    if (tid < DIM) hrow[tid] = hidden[(size_t)row * DIM + tid];
    if (tid < NSEG * DIM) sbias[tid] = bias[tid];
    if (tid == 0) { s_nhot = 0; }
    if (tid < 3) bcnt[tid] = 0;
    __syncthreads();

    const float4* row4 = (const float4*)(logits + (size_t)row * VOCAB);
    float4*       out4 = (float4*)(out + (size_t)row * VOCAB);
    const int NV4 = VOCAB / 4;   // 25000

    // ------- Pass 1: pipelined copy + collect (prefetch depth 1) ------------
    {
        int i0 = tid, i1 = tid + NTHREADS;
        bool ok0 = i0 < NV4, ok1 = i1 < NV4;
        float4 c0, c1;
        if (ok0) c0 = __ldcs(&row4[i0]);
        if (ok1) c1 = __ldcs(&row4[i1]);

        for (int base = 0; base < NV4; base += NTHREADS * 2) {
            // prefetch next iteration's loads FIRST
            int n0 = base + NTHREADS * 2 + tid;
            int n1 = n0 + NTHREADS;
            bool nok0 = n0 < NV4, nok1 = n1 < NV4;
            float4 p0, p1;
            if (nok0) p0 = __ldcs(&row4[n0]);
            if (nok1) p1 = __ldcs(&row4[n1]);

            // store current
            if (ok0) __stcs(&out4[base + tid], c0);
            if (ok1) __stcs(&out4[base + NTHREADS + tid], c1);

            // process current
            float M0 = ok0 ? fmaxf(fmaxf(c0.x, c0.y), fmaxf(c0.z, c0.w)) : -1e30f;
            float M1 = ok1 ? fmaxf(fmaxf(c1.x, c1.y), fmaxf(c1.z, c1.w)) : -1e30f;
            unsigned msk = 0;
            int cnt = 0;
            if (fmaxf(M0, M1) > TGUESS) {
                if (M0 > TGUESS)
                    msk |= (c0.x > TGUESS) | ((c0.y > TGUESS) << 1)
                         | ((c0.z > TGUESS) << 2) | ((c0.w > TGUESS) << 3);
                if (M1 > TGUESS)
                    msk |= ((c1.x > TGUESS) << 4) | ((c1.y > TGUESS) << 5)
                         | ((c1.z > TGUESS) << 6) | ((c1.w > TGUESS) << 7);
                cnt = __popc(msk);
            }

            if (__ballot_sync(0xFFFFFFFFu, cnt > 0)) {
                int pfx = cnt;
#pragma unroll
                for (int off = 1; off < 32; off <<= 1) {
                    int n = __shfl_up_sync(0xFFFFFFFFu, pfx, off);
                    if (lane >= off) pfx += n;
                }
                int total = __shfl_sync(0xFFFFFFFFu, pfx, 31);
                int wbase = 0;
                if (lane == 31) wbase = atomicAdd(&s_nhot, total);
                wbase = __shfl_sync(0xFFFFFFFFu, wbase, 31);
                int slot = wbase + pfx - cnt;
                if (cnt) {
                    push_group(c0, msk & 0xF,        4 * (base + tid),            hot, hist, slot);
                    push_group(c1, (msk >> 4) & 0xF, 4 * (base + NTHREADS + tid), hot, hist, slot);
                }
            }

            c0 = p0; c1 = p1; ok0 = nok0; ok1 = nok1;
        }
    }
    __syncthreads();

    // ------- In-CTA rh GEMV: 16 warps x 24 outputs, ILP-4 load groups -------
    {
        const float4* W4 = (const float4*)W;          // [384][32] float4
        const float4* h4 = (const float4*)hrow;
        float4 hv = h4[lane];
        const int o0 = wid * 24;
#pragma unroll
        for (int g = 0; g < 6; g++) {
            float4 wv[4];
#pragma unroll
            for (int k = 0; k < 4; k++)
                wv[k] = W4[(size_t)(o0 + g * 4 + k) * 32 + lane];
#pragma unroll
            for (int k = 0; k < 4; k++) {
                float p = wv[k].x * hv.x + wv[k].y * hv.y
                        + wv[k].z * hv.z + wv[k].w * hv.w;
                p += __shfl_xor_sync(0xFFFFFFFFu, p, 16);
                p += __shfl_xor_sync(0xFFFFFFFFu, p, 8);
                p += __shfl_xor_sync(0xFFFFFFFFu, p, 4);
                p += __shfl_xor_sync(0xFFFFFFFFu, p, 2);
                p += __shfl_xor_sync(0xFFFFFFFFu, p, 1);
                int o = o0 + g * 4 + k;
                if (lane == 0) rh[o] = p + sbias[o];
            }
        }
    }

    int nhot = s_nhot;
    bool fast = (nhot >= CUT2) && (nhot <= HOTCAP);

    if (fast) {
        scan_find(hist, warpsum, tid, s_bin, s_rank);
        const int b0 = s_bin[0], b1 = s_bin[1], b2 = s_bin[2];

        // ---- Gather boundary-bin members into tiny buffers (one pass) ----
        for (int i = tid; i < nhot; i += NTHREADS) {
            unsigned long long k = hot[i];
            int bin = (int)finebin((unsigned)(k >> 32));
            if (bin == b0) { int p = atomicAdd(&bcnt[0], 1); if (p < BCAP) bbuf[0][p] = k; }
            if (bin == b1) { int p = atomicAdd(&bcnt[1], 1); if (p < BCAP) bbuf[1][p] = k; }
            if (bin == b2) { int p = atomicAdd(&bcnt[2], 1); if (p < BCAP) bbuf[2][p] = k; }
        }
        __syncthreads();

        // ---- Exact threshold keys: count-greater within each tiny buffer ----
#pragma unroll
        for (int kk = 0; kk < 3; kk++) {
            int n = bcnt[kk];
            if (n <= BCAP) {
                for (int i = tid; i < n; i += NTHREADS) {
                    unsigned long long k = bbuf[kk][i];
                    int cnt = 0;
                    for (int j = 0; j < n; j++)
                        if (bbuf[kk][j] > k) cnt++;
                    if (cnt + 1 == s_rank[kk]) Tkey[kk] = k;
                }
            } else {
                // overflow (astronomically rare): scan the full hot[] set
                const int bk = s_bin[kk];
                for (int i = tid; i < nhot; i += NTHREADS) {
                    unsigned long long k = hot[i];
                    if ((int)finebin((unsigned)(k >> 32)) != bk) continue;
                    int cnt = 0;
                    for (int j = 0; j < nhot; j++) {
                        unsigned long long kj = hot[j];
                        if ((int)finebin((unsigned)(kj >> 32)) == bk && kj > k) cnt++;
                    }
                    if (cnt + 1 == s_rank[kk]) Tkey[kk] = k;
                }
            }
        }
        __syncthreads();
    } else {
        // ------- Fallback: full coarse histogram over the row (rare) -------
        for (int i = tid; i < NBINS; i += NTHREADS) hist[i] = 0u;
        if (tid == 0) s_nhot = 0;
        __syncthreads();
        for (int i = tid; i < NV4; i += NTHREADS) {
            float4 v = row4[i];
            atomicAdd(&hist[mono(v.x) >> 21], 1u);
            atomicAdd(&hist[mono(v.y) >> 21], 1u);
            atomicAdd(&hist[mono(v.z) >> 21], 1u);
            atomicAdd(&hist[mono(v.w) >> 21], 1u);
        }
        __syncthreads();
        scan_find(hist, warpsum, tid, s_bin, s_rank);
        const int cb2 = s_bin[2];
        for (int i = tid; i < NV4; i += NTHREADS) {
            float4 v = row4[i];
            float vals[4] = {v.x, v.y, v.z, v.w};
            int b4 = 4 * i;
#pragma unroll
            for (int j = 0; j < 4; j++) {
                unsigned m = mono(vals[j]);
                if ((int)(m >> 21) >= cb2) {
                    int p = atomicAdd(&s_nhot, 1);
                    if (p < HOTCAP)
                        hot[p] = ((unsigned long long)m << 32) | (unsigned)(~(b4 + j));
                }
            }
        }
        __syncthreads();
        nhot = (s_nhot < HOTCAP) ? s_nhot : HOTCAP;
        const int b0 = s_bin[0], b1 = s_bin[1], b2 = s_bin[2];
        for (int i = tid; i < nhot; i += NTHREADS) {
            unsigned long long k = hot[i];
            int bin = (int)(k >> 53);
            bool m0 = (bin == b0), m1 = (bin == b1), m2 = (bin == b2);
            if (m0 | m1 | m2) {
                int cnt = 0;
                for (int j = 0; j < nhot; j++) {
                    unsigned long long kj = hot[j];
                    if ((int)(kj >> 53) == bin && kj > k) cnt++;
                }
                int r = cnt + 1;
                if (m0 && r == s_rank[0]) Tkey[0] = k;
                if (m1 && r == s_rank[1]) Tkey[1] = k;
                if (m2 && r == s_rank[2]) Tkey[2] = k;
            }
        }
        __syncthreads();
    }

    const unsigned long long T0 = Tkey[0], T1 = Tkey[1], T2 = Tkey[2];

    // ------- Dot phase: 2 candidates per warp per round -------
    const int NW = NTHREADS / 32;
    const float4* emb4 = (const float4*)emb;
    const float4* rh4  = (const float4*)rh;
    float* outrow = out + (size_t)row * VOCAB;

    for (int s = wid * 2; s < nhot; s += NW * 2) {
        unsigned long long k[2];
        bool act[2];
        unsigned idx[2];
        float4 e[2];
        int seg[2];
#pragma unroll
        for (int j = 0; j < 2; j++) {
            int si = s + j;
            k[j] = (si < nhot) ? hot[si] : 0ull;
            act[j] = (k[j] >= T2);
            if (act[j]) {
                seg[j] = (k[j] >= T0) ? 0 : ((k[j] >= T1) ? 1 : 2);
                idx[j] = ~(unsigned)k[j];
                e[j] = emb4[(size_t)idx[j] * (DIM / 4) + lane];
            }
        }
#pragma unroll
        for (int j = 0; j < 2; j++) {
            if (!act[j]) continue;
            float4 r = rh4[seg[j] * (DIM / 4) + lane];
            float p = e[j].x * r.x + e[j].y * r.y + e[j].z * r.z + e[j].w * r.w;
            p += __shfl_xor_sync(0xFFFFFFFFu, p, 16);
            p += __shfl_xor_sync(0xFFFFFFFFu, p, 8);
            p += __shfl_xor_sync(0xFFFFFFFFu, p, 4);
            p += __shfl_xor_sync(0xFFFFFFFFu, p, 2);
            p += __shfl_xor_sync(0xFFFFFFFFu, p, 1);
            if (lane == 0) outrow[idx[j]] = p;
        }
    }
}

extern "C" void kernel_launch(void* const* d_in, const int* in_sizes, int n_in,
                              void* d_out, int out_size)
{
    const float* hidden = nullptr;
    const float* logits = nullptr;
    const float* emb    = nullptr;
    const float* W      = nullptr;
    const float* bias   = nullptr;
    for (int i = 0; i < n_in; i++) {
        switch (in_sizes[i]) {
            case BATCH * DIM:      hidden = (const float*)d_in[i]; break;
            case BATCH * VOCAB:    logits = (const float*)d_in[i]; break;
            case VOCAB * DIM:      emb    = (const float*)d_in[i]; break;
            case NSEG * DIM * DIM: W      = (const float*)d_in[i]; break;
            case NSEG * DIM:       bias   = (const float*)d_in[i]; break;
        }
    }
    float* out = (float*)d_out;

    rerank_kernel<<<BATCH, NTHREADS>>>(logits, emb, hidden, W, bias, out);
}

// round 17
// speedup vs baseline: 1.5850x; 1.0148x over previous
#include <cuda_runtime.h>
#include <cstdint>

#define BATCH    1024
#define VOCAB    100000
#define DIM      128
#define NSEG     3
#define NBINS    2048
#define PSLOT    8
#define OVFCAP   256
#define BCAP     96
#define NTHREADS 512
#define NSLOTS   (NTHREADS * PSLOT)     // 4096
#define CUT0 100
#define CUT1 500
#define CUT2 1000
#define TGUESS 2.0f          // rank-1000 of 100k N(0,1) ~ 2.33; P(v>2)~2.3% -> ~2275 cands

#define NV4      (VOCAB / 4)                       // 25000
#define FULLIT   (NV4 / (NTHREADS * 2))            // 24 full iterations
#define MAIN4    (FULLIT * NTHREADS * 2)           // 24576
#define TAIL4    (NV4 - MAIN4)                     // 424

__device__ __forceinline__ unsigned mono(float f) {
    unsigned u = __float_as_uint(f);
    return (u & 0x80000000u) ? ~u : (u | 0x80000000u);
}

__device__ __forceinline__ unsigned finebin(unsigned m) {
    unsigned fb = (m - 0xC0000000u) >> 13;       // BASE = mono(2.0f), 2048 bins
    return (fb > (NBINS - 1u)) ? (NBINS - 1u) : fb;
}

// ---------------------------------------------------------------------------
// Scan NBINS-bin histogram descending with shfl; 4 bins per thread.
// ---------------------------------------------------------------------------
__device__ void scan_find(unsigned* hist, unsigned* warpsum, int tid,
                          int* s_bin, int* s_rank)
{
    const int lane = tid & 31, w = tid >> 5;
    unsigned c[4];
    unsigned chunk = 0;
#pragma unroll
    for (int j = 0; j < 4; j++) {
        c[j] = hist[NBINS - 1 - 4 * tid - j];
        chunk += c[j];
    }
    unsigned pfx = chunk;
#pragma unroll
    for (int off = 1; off < 32; off <<= 1) {
        unsigned n = __shfl_up_sync(0xFFFFFFFFu, pfx, off);
        if (lane >= off) pfx += n;
    }
    if (lane == 31) warpsum[w] = pfx;
    __syncthreads();
    if (w == 0) {
        unsigned s = (lane < 16) ? warpsum[lane] : 0u;
#pragma unroll
        for (int off = 1; off < 16; off <<= 1) {
            unsigned n = __shfl_up_sync(0xFFFFFFFFu, s, off);
            if (lane >= off) s += n;
        }
        if (lane < 16) warpsum[lane] = s;
    }
    __syncthreads();
    unsigned wbase = (w > 0) ? warpsum[w - 1] : 0u;
    unsigned incl = wbase + pfx;
    unsigned excl = incl - chunk;
    const unsigned Ks[3] = {CUT0, CUT1, CUT2};
#pragma unroll
    for (int kk = 0; kk < 3; kk++) {
        unsigned K = Ks[kk];
        if (excl < K && K <= incl) {
            unsigned cc = excl;
#pragma unroll
            for (int j = 0; j < 4; j++) {
                unsigned h = c[j];
                if (cc < K && K <= cc + h) {
                    s_bin[kk]  = NBINS - 1 - 4 * tid - j;
                    s_rank[kk] = (int)(K - cc);
                    break;
                }
                cc += h;
            }
        }
    }
    __syncthreads();
}

// ---------------------------------------------------------------------------
// Single fused kernel: one CTA (512 thr) per row.
// Pass 1: copy + thread-private candidate capture (no cross-lane deps).
// Then: per-thread hist, rh GEMV, exact selection, dot + scatter.
// ---------------------------------------------------------------------------
__global__ void __launch_bounds__(NTHREADS, 4)
rerank_kernel(const float* __restrict__ logits,
              const float* __restrict__ emb,
              const float* __restrict__ hidden,
              const float* __restrict__ W,
              const float* __restrict__ bias,
              float* __restrict__ out)
{
    __shared__ unsigned long long priv[NSLOTS];      // 32 KB thread-private slots
    __shared__ unsigned long long ovf[OVFCAP];       // 2 KB overflow
    __shared__ unsigned hist[NBINS];                 // 8 KB
    __shared__ unsigned long long bbuf[3][BCAP];     // 2.25 KB boundary-bin members
    __shared__ unsigned warpsum[16];
    __shared__ float rh[NSEG * DIM];
    __shared__ float sbias[NSEG * DIM];
    __shared__ float hrow[DIM];
    __shared__ unsigned long long Tkey[3];
    __shared__ int s_bin[3];
    __shared__ int s_rank[3];
    __shared__ int bcnt[3];
    __shared__ int s_nhot;
    __shared__ int s_ovf;

    const int row = blockIdx.x;
    const int tid = threadIdx.x;
    const int lane = tid & 31;
    const int wid = tid >> 5;

    for (int i = tid; i < NBINS; i += NTHREADS) hist[i] = 0u;
#pragma unroll
    for (int c = 0; c < PSLOT; c++) priv[c * NTHREADS + tid] = 0ull;
    if (tid < DIM) hrow[tid] = hidden[(size_t)row * DIM + tid];
    if (tid < NSEG * DIM) sbias[tid] = bias[tid];
    if (tid == 0) { s_nhot = 0; s_ovf = 0; }
    if (tid < 3) bcnt[tid] = 0;
    __syncthreads();

    const float4* row4 = (const float4*)(logits + (size_t)row * VOCAB);
    float4*       out4 = (float4*)(out + (size_t)row * VOCAB);

    // ------- Pass 1: copy + private capture; no warp-collective ops ---------
    int cnt = 0;
    for (int it = 0; it < FULLIT; it++) {             // full iterations: no bounds
        const int i0 = it * (NTHREADS * 2) + tid;
        const int i1 = i0 + NTHREADS;
        float4 v0 = __ldcs(&row4[i0]);
        float4 v1 = __ldcs(&row4[i1]);
        __stcs(&out4[i0], v0);
        __stcs(&out4[i1], v1);

        float M0 = fmaxf(fmaxf(v0.x, v0.y), fmaxf(v0.z, v0.w));
        float M1 = fmaxf(fmaxf(v1.x, v1.y), fmaxf(v1.z, v1.w));
        if (fmaxf(M0, M1) > TGUESS) {                 // ~17% of threads
            float vals[8] = {v0.x, v0.y, v0.z, v0.w, v1.x, v1.y, v1.z, v1.w};
            int   gidx[8] = {4*i0, 4*i0+1, 4*i0+2, 4*i0+3,
                             4*i1, 4*i1+1, 4*i1+2, 4*i1+3};
#pragma unroll
            for (int q = 0; q < 8; q++) {
                if (vals[q] > TGUESS) {
                    unsigned long long k =
                        ((unsigned long long)mono(vals[q]) << 32) | (unsigned)(~gidx[q]);
                    if (cnt < PSLOT) {
                        priv[cnt * NTHREADS + tid] = k;
                    } else {
                        int p = atomicAdd(&s_ovf, 1);
                        if (p < OVFCAP) ovf[p] = k;
                    }
                    cnt++;
                }
            }
        }
    }
    // tail: TAIL4 float4 groups, guarded per-element
    if (tid < TAIL4) {
        const int i = MAIN4 + tid;
        float4 v = __ldcs(&row4[i]);
        __stcs(&out4[i], v);
        if (fmaxf(fmaxf(v.x, v.y), fmaxf(v.z, v.w)) > TGUESS) {
            float vals[4] = {v.x, v.y, v.z, v.w};
#pragma unroll
            for (int q = 0; q < 4; q++) {
                if (vals[q] > TGUESS) {
                    unsigned long long k =
                        ((unsigned long long)mono(vals[q]) << 32) | (unsigned)(~(4 * i + q));
                    if (cnt < PSLOT) {
                        priv[cnt * NTHREADS + tid] = k;
                    } else {
                        int p = atomicAdd(&s_ovf, 1);
                        if (p < OVFCAP) ovf[p] = k;
                    }
                    cnt++;
                }
            }
        }
    }
    // warp-reduce candidate counts -> nhot (once, not per iteration)
    {
        int t = cnt;
#pragma unroll
        for (int off = 16; off > 0; off >>= 1)
            t += __shfl_xor_sync(0xFFFFFFFFu, t, off);
        if (lane == 0) atomicAdd(&s_nhot, t);
    }
    __syncthreads();

    const int myents = (cnt < PSLOT) ? cnt : PSLOT;
    const int nhot = s_nhot;
    const int ovfn = (s_ovf < OVFCAP) ? s_ovf : OVFCAP;
    bool fast = (nhot >= CUT2) && (s_ovf <= OVFCAP);

    if (fast) {
        // ---- Per-thread fine histogram of own entries + overflow ----
        for (int c = 0; c < myents; c++)
            atomicAdd(&hist[finebin((unsigned)(priv[c * NTHREADS + tid] >> 32))], 1u);
        for (int i = tid; i < ovfn; i += NTHREADS)
            atomicAdd(&hist[finebin((unsigned)(ovf[i] >> 32))], 1u);
        __syncthreads();
    }

    // ------- In-CTA rh GEMV: 16 warps x 24 outputs, ILP-4 load groups -------
    {
        const float4* W4 = (const float4*)W;          // [384][32] float4
        const float4* h4 = (const float4*)hrow;
        float4 hv = h4[lane];
        const int o0 = wid * 24;
#pragma unroll
        for (int g = 0; g < 6; g++) {
            float4 wv[4];
#pragma unroll
            for (int k = 0; k < 4; k++)
                wv[k] = W4[(size_t)(o0 + g * 4 + k) * 32 + lane];
#pragma unroll
            for (int k = 0; k < 4; k++) {
                float p = wv[k].x * hv.x + wv[k].y * hv.y
                        + wv[k].z * hv.z + wv[k].w * hv.w;
                p += __shfl_xor_sync(0xFFFFFFFFu, p, 16);
                p += __shfl_xor_sync(0xFFFFFFFFu, p, 8);
                p += __shfl_xor_sync(0xFFFFFFFFu, p, 4);
                p += __shfl_xor_sync(0xFFFFFFFFu, p, 2);
                p += __shfl_xor_sync(0xFFFFFFFFu, p, 1);
                int o = o0 + g * 4 + k;
                if (lane == 0) rh[o] = p + sbias[o];
            }
        }
    }

    if (fast) {
        scan_find(hist, warpsum, tid, s_bin, s_rank);
        const int b0 = s_bin[0], b1 = s_bin[1], b2 = s_bin[2];

        // ---- Gather boundary-bin members: own entries + overflow ----
        for (int c = 0; c < myents; c++) {
            unsigned long long k = priv[c * NTHREADS + tid];
            int bin = (int)finebin((unsigned)(k >> 32));
            if (bin == b0) { int p = atomicAdd(&bcnt[0], 1); if (p < BCAP) bbuf[0][p] = k; }
            if (bin == b1) { int p = atomicAdd(&bcnt[1], 1); if (p < BCAP) bbuf[1][p] = k; }
            if (bin == b2) { int p = atomicAdd(&bcnt[2], 1); if (p < BCAP) bbuf[2][p] = k; }
        }
        for (int i = tid; i < ovfn; i += NTHREADS) {
            unsigned long long k = ovf[i];
            int bin = (int)finebin((unsigned)(k >> 32));
            if (bin == b0) { int p = atomicAdd(&bcnt[0], 1); if (p < BCAP) bbuf[0][p] = k; }
            if (bin == b1) { int p = atomicAdd(&bcnt[1], 1); if (p < BCAP) bbuf[1][p] = k; }
            if (bin == b2) { int p = atomicAdd(&bcnt[2], 1); if (p < BCAP) bbuf[2][p] = k; }
        }
        __syncthreads();

        // ---- Exact threshold keys: count-greater within each tiny buffer ----
        bool bover = (bcnt[0] > BCAP) | (bcnt[1] > BCAP) | (bcnt[2] > BCAP);
        if (!bover) {
#pragma unroll
            for (int kk = 0; kk < 3; kk++) {
                int n = bcnt[kk];
                for (int i = tid; i < n; i += NTHREADS) {
                    unsigned long long k = bbuf[kk][i];
                    int cg = 0;
                    for (int j = 0; j < n; j++)
                        if (bbuf[kk][j] > k) cg++;
                    if (cg + 1 == s_rank[kk]) Tkey[kk] = k;
                }
            }
        } else {
            fast = false;                             // fall through to slow path
        }
        __syncthreads();
    }

    if (!fast) {
        // ------- Fallback: full coarse histogram over the row (rare) -------
        // Reuse priv[] as a hot buffer.
        for (int i = tid; i < NBINS; i += NTHREADS) hist[i] = 0u;
        if (tid == 0) { s_nhot = 0; }
        __syncthreads();
        for (int i = tid; i < NV4; i += NTHREADS) {
            float4 v = row4[i];
            atomicAdd(&hist[mono(v.x) >> 21], 1u);
            atomicAdd(&hist[mono(v.y) >> 21], 1u);
            atomicAdd(&hist[mono(v.z) >> 21], 1u);
            atomicAdd(&hist[mono(v.w) >> 21], 1u);
        }
        __syncthreads();
        scan_find(hist, warpsum, tid, s_bin, s_rank);
        const int cb2 = s_bin[2];
        for (int i = tid; i < NV4; i += NTHREADS) {
            float4 v = row4[i];
            float vals[4] = {v.x, v.y, v.z, v.w};
            int b4 = 4 * i;
#pragma unroll
            for (int j = 0; j < 4; j++) {
                unsigned m = mono(vals[j]);
                if ((int)(m >> 21) >= cb2) {
                    int p = atomicAdd(&s_nhot, 1);
                    if (p < NSLOTS)
                        priv[p] = ((unsigned long long)m << 32) | (unsigned)(~(b4 + j));
                }
            }
        }
        __syncthreads();
        int nh = (s_nhot < NSLOTS) ? s_nhot : NSLOTS;
        const int b0 = s_bin[0], b1 = s_bin[1], b2 = s_bin[2];
        for (int i = tid; i < nh; i += NTHREADS) {
            unsigned long long k = priv[i];
            int bin = (int)(k >> 53);
            bool m0 = (bin == b0), m1 = (bin == b1), m2 = (bin == b2);
            if (m0 | m1 | m2) {
                int cg = 0;
                for (int j = 0; j < nh; j++) {
                    unsigned long long kj = priv[j];
                    if ((int)(kj >> 53) == bin && kj > k) cg++;
                }
                int r = cg + 1;
                if (m0 && r == s_rank[0]) Tkey[0] = k;
                if (m1 && r == s_rank[1]) Tkey[1] = k;
                if (m2 && r == s_rank[2]) Tkey[2] = k;
            }
        }
        __syncthreads();
        // zero remaining slots so the shared dot loop skips them
        for (int i = nh + tid; i < NSLOTS; i += NTHREADS) priv[i] = 0ull;
        __syncthreads();
    }

    const unsigned long long T0 = Tkey[0], T1 = Tkey[1], T2 = Tkey[2];
    const int ovfn2 = fast ? ovfn : 0;

    // ------- Dot phase: iterate all slots; empty (0) slots auto-skip --------
    const int NW = NTHREADS / 32;
    const int TOT = NSLOTS + ovfn2;
    const float4* emb4 = (const float4*)emb;
    const float4* rh4  = (const float4*)rh;
    float* outrow = out + (size_t)row * VOCAB;

    for (int s = wid * 2; s < TOT; s += NW * 2) {
        unsigned long long k[2];
        bool act[2];
        unsigned idx[2];
        float4 e[2];
        int seg[2];
#pragma unroll
        for (int j = 0; j < 2; j++) {
            int si = s + j;
            k[j] = (si < NSLOTS) ? priv[si] : ((si < TOT) ? ovf[si - NSLOTS] : 0ull);
            act[j] = (k[j] >= T2);
            if (act[j]) {
                seg[j] = (k[j] >= T0) ? 0 : ((k[j] >= T1) ? 1 : 2);
                idx[j] = ~(unsigned)k[j];
                e[j] = emb4[(size_t)idx[j] * (DIM / 4) + lane];
            }
        }
#pragma unroll
        for (int j = 0; j < 2; j++) {
            if (!act[j]) continue;
            float4 r = rh4[seg[j] * (DIM / 4) + lane];
            float p = e[j].x * r.x + e[j].y * r.y + e[j].z * r.z + e[j].w * r.w;
            p += __shfl_xor_sync(0xFFFFFFFFu, p, 16);
            p += __shfl_xor_sync(0xFFFFFFFFu, p, 8);
            p += __shfl_xor_sync(0xFFFFFFFFu, p, 4);
            p += __shfl_xor_sync(0xFFFFFFFFu, p, 2);
            p += __shfl_xor_sync(0xFFFFFFFFu, p, 1);
            if (lane == 0) outrow[idx[j]] = p;
        }
    }
}

extern "C" void kernel_launch(void* const* d_in, const int* in_sizes, int n_in,
                              void* d_out, int out_size)
{
    const float* hidden = nullptr;
    const float* logits = nullptr;
    const float* emb    = nullptr;
    const float* W      = nullptr;
    const float* bias   = nullptr;
    for (int i = 0; i < n_in; i++) {
        switch (in_sizes[i]) {
            case BATCH * DIM:      hidden = (const float*)d_in[i]; break;
            case BATCH * VOCAB:    logits = (const float*)d_in[i]; break;
            case VOCAB * DIM:      emb    = (const float*)d_in[i]; break;
            case NSEG * DIM * DIM: W      = (const float*)d_in[i]; break;
            case NSEG * DIM:       bias   = (const float*)d_in[i]; break;
        }
    }
    float* out = (float*)d_out;

    rerank_kernel<<<BATCH, NTHREADS>>>(logits, emb, hidden, W, bias, out);
}